// round 13
// baseline (speedup 1.0000x reference)
#include <cuda_runtime.h>
#include <cuda_pipeline.h>

// Mat2Twist: rotation matrix (3x3) -> axis-angle (3). Memory-bound.
//
// R13 (corrected): flat launch, 4 tiles/CTA on a 2-buffer cp.async ring.
//   - R12 proven parts: flat grid, cp.async staging, R7 tile geometry,
//     __stcs streaming stores. smem 24.6KB -> 8 CTAs/SM.
//   - 4 tiles amortize the prologue; compute+store of tile k overlaps the
//     in-flight loads of tile k+1; refill of tile k+2 is issued only after
//     tile k's smem reads are done (compute finishes before the store
//     barrier inside compute_store_tile orders them).
// Bench-wall hypothesis under test: 201.3MB compulsory / 33.248us = 6.05TB/s.

#define TPB   256
#define MATS  256
#define F4T   ((MATS * 9) / 4)   // 576 float4 per tile
#define TILES_PER_CTA 4
#define MPB   (TILES_PER_CTA * MATS)   // 1024 matrices per CTA

__device__ __forceinline__ void prefetch_tile(
    const float4* __restrict__ gin4, int tile, float4* dst, int tid)
{
    const float4* src = gin4 + (size_t)tile * F4T;
    __pipeline_memcpy_async(dst + tid,       src + tid,       16);
    __pipeline_memcpy_async(dst + tid + TPB, src + tid + TPB, 16);
    if (tid < F4T - 2 * TPB)
        __pipeline_memcpy_async(dst + tid + 2 * TPB, src + tid + 2 * TPB, 16);
}

__global__ __launch_bounds__(TPB) void mat2twist_kernel(
    const float* __restrict__ in, float* __restrict__ out,
    int n, int nFullTiles)
{
    __shared__ float4 s_in[2][F4T];          // 2 * 9216 B
    __shared__ float  s_out[2][MATS * 3];    // 2 * 3072 B

    const int tid = threadIdx.x;
    const float4* __restrict__ gin4 = reinterpret_cast<const float4*>(in);
    const int base = blockIdx.x * TILES_PER_CTA;

    // ---- prologue: prefetch tiles 0 and 1, one commit group each ----
    if (base < nFullTiles) prefetch_tile(gin4, base, s_in[0], tid);
    __pipeline_commit();
    if (base + 1 < nFullTiles) prefetch_tile(gin4, base + 1, s_in[1], tid);
    __pipeline_commit();

    #pragma unroll
    for (int k = 0; k < TILES_PER_CTA; k++) {
        const int tile = base + k;
        if (tile >= nFullTiles) break;
        const int buf = k & 1;

        // Exactly one group has been committed after tile k's group
        // (tile k+1's, or an empty one) -> wait_prior(1) completes tile k.
        __pipeline_wait_prior(1);
        __syncthreads();

        // ---- compute tile k from s_in[buf] ----
        {
            const float* m = reinterpret_cast<const float*>(s_in[buf]) + tid * 9;
            float m00 = m[0], m01 = m[1], m02 = m[2];
            float m10 = m[3], m11 = m[4], m12 = m[5];
            float m20 = m[6], m21 = m[7], m22 = m[8];

            float c = 0.5f * (m00 + m11 + m22 - 1.0f);
            c = fminf(1.0f, fmaxf(-1.0f, c));
            // sin(acos(c)) = sqrt(1-c^2); theta in [0.1, pi-0.1] keeps it safe
            float scale = 0.5f * acosf(c) * rsqrtf(fmaxf(1.0f - c * c, 1e-12f));

            s_out[buf][tid * 3 + 0] = scale * (m21 - m12);
            s_out[buf][tid * 3 + 1] = scale * (m02 - m20);
            s_out[buf][tid * 3 + 2] = scale * (m10 - m01);
        }
        __syncthreads();   // all smem reads of s_in[buf] complete block-wide

        // ---- refill this buffer with tile k+2 (safe now), overlap store ----
        if (tile + 2 < nFullTiles)
            prefetch_tile(gin4, tile + 2, s_in[buf], tid);
        __pipeline_commit();

        // ---- coalesced store of tile k: 192 float4 ----
        float4* __restrict__ gout =
            reinterpret_cast<float4*>(out + (size_t)tile * MATS * 3);
        const float4* so4 = reinterpret_cast<const float4*>(s_out[buf]);
        if (tid < (MATS * 3) / 4)
            __stcs(gout + tid, so4[tid]);
    }

    // ---- tail: matrices beyond the last full tile (scalar) ----
    int tailStart = nFullTiles * MATS;
    for (int i = tailStart + blockIdx.x * TPB + tid; i < n;
         i += gridDim.x * TPB) {
        const float* m = in + (size_t)i * 9;
        float m00 = m[0], m01 = m[1], m02 = m[2];
        float m10 = m[3], m11 = m[4], m12 = m[5];
        float m20 = m[6], m21 = m[7], m22 = m[8];

        float c = 0.5f * (m00 + m11 + m22 - 1.0f);
        c = fminf(1.0f, fmaxf(-1.0f, c));
        float scale = 0.5f * acosf(c) * rsqrtf(fmaxf(1.0f - c * c, 1e-12f));

        out[(size_t)i * 3 + 0] = scale * (m21 - m12);
        out[(size_t)i * 3 + 1] = scale * (m02 - m20);
        out[(size_t)i * 3 + 2] = scale * (m10 - m01);
    }
}

extern "C" void kernel_launch(void* const* d_in, const int* in_sizes, int n_in,
                              void* d_out, int out_size)
{
    const float* in = (const float*)d_in[0];
    float* out = (float*)d_out;
    int n = in_sizes[0] / 9;            // number of matrices
    int nFullTiles = n / MATS;

    int grid = (n + MPB - 1) / MPB;     // 4 tiles per CTA, non-persistent
    if (grid < 1) grid = 1;

    mat2twist_kernel<<<grid, TPB>>>(in, out, n, nFullTiles);
}

// round 16
// speedup vs baseline: 1.0500x; 1.0500x over previous
#include <cuda_runtime.h>
#include <cstdint>

// Mat2Twist: rotation matrix (3x3) -> axis-angle (3). Memory-bound.
//
// R14: R12's two-tile flat structure, but all global traffic via bulk TMA.
//   - loads:  one cp.async.bulk (9216 B) per tile, mbarrier completion
//   - stores: one cp.async.bulk store (3072 B) per tile, bulk_group
//   - near-zero SM-side issue cost per byte; input bypasses L1/regs
//   - flat grid (no persistent penalty), 24.6KB smem -> 8 CTAs/SM
// Bench-wall check: R7/R12 both printed exactly 33.248us (= 201.3MB at
// ~6.05 TB/s). If this kernel profiles faster but benches 33.25 again,
// the wall is confirmed.

#define TPB   256
#define MATS  256
#define TILE_IN_B  (MATS * 9 * 4)   // 9216
#define TILE_OUT_B (MATS * 3 * 4)   // 3072
#define MPB   (2 * MATS)            // 512 matrices per CTA

__device__ __forceinline__ uint32_t smem_u32(const void* p) {
    uint32_t a;
    asm("{ .reg .u64 t; cvta.to.shared.u64 t, %1; cvt.u32.u64 %0, t; }"
        : "=r"(a) : "l"(p));
    return a;
}

__device__ __forceinline__ void mbar_init(uint32_t mbar, uint32_t count) {
    asm volatile("mbarrier.init.shared.b64 [%0], %1;"
                 :: "r"(mbar), "r"(count) : "memory");
}
__device__ __forceinline__ void mbar_expect_tx(uint32_t mbar, uint32_t bytes) {
    asm volatile("mbarrier.arrive.expect_tx.shared.b64 _, [%0], %1;"
                 :: "r"(mbar), "r"(bytes) : "memory");
}
__device__ __forceinline__ void mbar_wait(uint32_t mbar, uint32_t parity) {
    asm volatile(
        "{\n\t"
        ".reg .pred P;\n\t"
        "WAIT_%=:\n\t"
        "mbarrier.try_wait.parity.acquire.cta.shared::cta.b64 P, [%0], %1, 0x989680;\n\t"
        "@P bra.uni DONE_%=;\n\t"
        "bra.uni WAIT_%=;\n\t"
        "DONE_%=:\n\t"
        "}"
        :: "r"(mbar), "r"(parity) : "memory");
}
__device__ __forceinline__ void bulk_ld(uint32_t smem_dst, const void* gsrc,
                                        uint32_t bytes, uint32_t mbar) {
    asm volatile(
        "cp.async.bulk.shared::cta.global.mbarrier::complete_tx::bytes "
        "[%0], [%1], %2, [%3];"
        :: "r"(smem_dst), "l"(gsrc), "r"(bytes), "r"(mbar) : "memory");
}
__device__ __forceinline__ void bulk_st(void* gdst, uint32_t smem_src,
                                        uint32_t bytes) {
    asm volatile(
        "cp.async.bulk.global.shared::cta.bulk_group [%0], [%1], %2;"
        :: "l"(gdst), "r"(smem_src), "r"(bytes) : "memory");
}

__global__ __launch_bounds__(TPB) void mat2twist_kernel(
    const float* __restrict__ in, float* __restrict__ out,
    int n, int nFullTiles)
{
    __shared__ alignas(16) uint64_t mbar[2];
    __shared__ alignas(16) float s_in[2][MATS * 9];   // 2 * 9216 B
    __shared__ alignas(16) float s_out[2][MATS * 3];  // 2 * 3072 B

    const int tid = threadIdx.x;
    const int t0 = blockIdx.x * 2;
    const int t1 = t0 + 1;

    const uint32_t mb0 = smem_u32(&mbar[0]);
    const uint32_t mb1 = smem_u32(&mbar[1]);

    if (tid == 0) {
        mbar_init(mb0, 1);
        mbar_init(mb1, 1);
    }
    __syncthreads();

    // ---- issue both tile loads (one bulk copy each) ----
    if (tid == 0) {
        if (t0 < nFullTiles) {
            mbar_expect_tx(mb0, TILE_IN_B);
            bulk_ld(smem_u32(s_in[0]), in + (size_t)t0 * MATS * 9,
                    TILE_IN_B, mb0);
        }
        if (t1 < nFullTiles) {
            mbar_expect_tx(mb1, TILE_IN_B);
            bulk_ld(smem_u32(s_in[1]), in + (size_t)t1 * MATS * 9,
                    TILE_IN_B, mb1);
        }
    }

    #pragma unroll
    for (int k = 0; k < 2; k++) {
        const int tile = (k == 0) ? t0 : t1;
        if (tile >= nFullTiles) break;

        // wait for this tile's data (phase 0: each mbarrier used once)
        mbar_wait(k == 0 ? mb0 : mb1, 0);

        // ---- compute ----
        const float* m = &s_in[k][tid * 9];
        float m00 = m[0], m01 = m[1], m02 = m[2];
        float m10 = m[3], m11 = m[4], m12 = m[5];
        float m20 = m[6], m21 = m[7], m22 = m[8];

        float c = 0.5f * (m00 + m11 + m22 - 1.0f);
        c = fminf(1.0f, fmaxf(-1.0f, c));
        // sin(acos(c)) = sqrt(1-c^2); theta in [0.1, pi-0.1] keeps this safe
        float scale = 0.5f * acosf(c) * rsqrtf(fmaxf(1.0f - c * c, 1e-12f));

        s_out[k][tid * 3 + 0] = scale * (m21 - m12);
        s_out[k][tid * 3 + 1] = scale * (m02 - m20);
        s_out[k][tid * 3 + 2] = scale * (m10 - m01);
        __syncthreads();

        // ---- one bulk TMA store for the whole tile ----
        if (tid == 0) {
            asm volatile("fence.proxy.async.shared::cta;" ::: "memory");
            bulk_st(out + (size_t)tile * MATS * 3, smem_u32(s_out[k]),
                    TILE_OUT_B);
            asm volatile("cp.async.bulk.commit_group;" ::: "memory");
        }
    }

    // drain pending bulk stores before exit (only tid 0 issued any)
    if (tid == 0)
        asm volatile("cp.async.bulk.wait_group 0;" ::: "memory");

    // ---- tail: matrices beyond the last full tile (scalar) ----
    int tailStart = nFullTiles * MATS;
    for (int i = tailStart + blockIdx.x * TPB + tid; i < n;
         i += gridDim.x * TPB) {
        const float* mm = in + (size_t)i * 9;
        float m00 = mm[0], m01 = mm[1], m02 = mm[2];
        float m10 = mm[3], m11 = mm[4], m12 = mm[5];
        float m20 = mm[6], m21 = mm[7], m22 = mm[8];

        float c = 0.5f * (m00 + m11 + m22 - 1.0f);
        c = fminf(1.0f, fmaxf(-1.0f, c));
        float scale = 0.5f * acosf(c) * rsqrtf(fmaxf(1.0f - c * c, 1e-12f));

        out[(size_t)i * 3 + 0] = scale * (m21 - m12);
        out[(size_t)i * 3 + 1] = scale * (m02 - m20);
        out[(size_t)i * 3 + 2] = scale * (m10 - m01);
    }
}

extern "C" void kernel_launch(void* const* d_in, const int* in_sizes, int n_in,
                              void* d_out, int out_size)
{
    const float* in = (const float*)d_in[0];
    float* out = (float*)d_out;
    int n = in_sizes[0] / 9;            // number of matrices
    int nFullTiles = n / MATS;

    int grid = (n + MPB - 1) / MPB;     // 2 tiles per CTA, non-persistent
    if (grid < 1) grid = 1;

    mat2twist_kernel<<<grid, TPB>>>(in, out, n, nFullTiles);
}